// round 1
// baseline (speedup 1.0000x reference)
#include <cuda_runtime.h>
#include <cstddef>

// Problem constants (fixed shapes from reference)
#define BB   4
#define NPIX 4096      // H*W = 64*64
#define C0   512       // content / V channels
#define C1   960       // comb channels
#define NVV  1024      // [V | V*V] concatenated width

// ---------------- scratch (device globals; no allocation allowed) ----------------
static __device__ float g_Xqn[(size_t)BB * NPIX * C1];   // normalized comb_cont
static __device__ float g_Xkn[(size_t)BB * NPIX * C1];   // normalized comb_sty
static __device__ float g_Q  [(size_t)BB * NPIX * C1];
static __device__ float g_Kk [(size_t)BB * NPIX * C1];
static __device__ float g_VV [(size_t)BB * NPIX * NVV];  // [V | V^2]
static __device__ float g_A  [(size_t)BB * NPIX * NPIX]; // attention (268 MB)
static __device__ float g_MV [(size_t)BB * NPIX * NVV];  // [M | E2]

// stats layout (sums -> later mean/rstd at identical offsets in g_norms):
//   [0,           BB*C0)              content sum   / mean
//   [BB*C0,       2*BB*C0)            content sumsq / rstd
//   [2*BB*C0,     2*BB*C0+BB*C1)      comb_cont sum / mean
//   [+BB*C1, ...]                     comb_cont ssq / rstd
//   then comb_sty sum/mean, ssq/rstd
#define NSTAT (2 * BB * C0 + 4 * BB * C1)   // 19456
static __device__ float g_sums [NSTAT];
static __device__ float g_norms[NSTAT];

// ---------------- small kernels ----------------

__global__ void zero_kernel(float* __restrict__ p, int n) {
    int i = blockIdx.x * 256 + threadIdx.x;
    if (i < n) p[i] = 0.f;
}

// Per-(b,channel) partial sums over a 128-row spatial chunk; atomically combined.
__global__ __launch_bounds__(128)
void stats_partial(const float* __restrict__ X, float* __restrict__ sum,
                   float* __restrict__ ssq, int Cx) {
    const int c = blockIdx.x * 128 + threadIdx.x;
    if (c >= Cx) return;
    const int b = blockIdx.z;
    const int chunk = blockIdx.y;                    // 32 chunks of 128 rows
    const float* p = X + ((size_t)b * NPIX + (size_t)chunk * 128) * Cx + c;
    float s = 0.f, s2 = 0.f;
#pragma unroll 8
    for (int n = 0; n < 128; n++) {
        float x = p[(size_t)n * Cx];
        s += x;
        s2 = fmaf(x, x, s2);
    }
    atomicAdd(&sum[b * Cx + c], s);
    atomicAdd(&ssq[b * Cx + c], s2);
}

__global__ void stats_finalize_kernel() {
    const int nch = BB * C0 + 2 * BB * C1;           // 9728
    int i = blockIdx.x * 256 + threadIdx.x;
    if (i >= nch) return;
    int sum_idx, ssq_idx;
    if (i < BB * C0) {
        sum_idx = i;
        ssq_idx = BB * C0 + i;
    } else if (i < BB * C0 + BB * C1) {
        int j = i - BB * C0;
        sum_idx = 2 * BB * C0 + j;
        ssq_idx = 2 * BB * C0 + BB * C1 + j;
    } else {
        int j = i - BB * C0 - BB * C1;
        sum_idx = 2 * BB * C0 + 2 * BB * C1 + j;
        ssq_idx = sum_idx + BB * C1;
    }
    float m   = g_sums[sum_idx] * (1.f / NPIX);
    float var = g_sums[ssq_idx] * (1.f / NPIX) - m * m;
    g_norms[sum_idx] = m;
    g_norms[ssq_idx] = rsqrtf(var + 1e-5f);
}

// Elementwise instance-norm apply (C1-wide tensors), float4 vectorized (C1 % 4 == 0).
__global__ __launch_bounds__(256)
void normalize_kernel(const float* __restrict__ X, float* __restrict__ Y,
                      const float* __restrict__ mean, const float* __restrict__ rstd) {
    size_t i4 = ((size_t)blockIdx.x * 256 + threadIdx.x) * 4;
    const size_t total = (size_t)BB * NPIX * C1;
    if (i4 >= total) return;
    int c = (int)(i4 % C1);
    int b = (int)(i4 / ((size_t)NPIX * C1));
    float4 x = *reinterpret_cast<const float4*>(X + i4);
    const float* mp = mean + b * C1 + c;
    const float* rp = rstd + b * C1 + c;
    float4 y;
    y.x = (x.x - mp[0]) * rp[0];
    y.y = (x.y - mp[1]) * rp[1];
    y.z = (x.z - mp[2]) * rp[2];
    y.w = (x.w - mp[3]) * rp[3];
    *reinterpret_cast<float4*>(Y + i4) = y;
}

// ---------------- GEMM: 128x128x8 blocktile, 8x8 per thread, fp32 SIMT ----------------
// TRANSB=false: C[m,n] = sum_k A[m,k] * B[k,n]   (B row-major [K,N])
// TRANSB=true : C[m,n] = sum_k A[m,k] * B[n,k]   (B row-major [N,K])
// VSQ=true    : also writes v*v at column offset ldc/2 (for [V | V^2])
// Requirements used here: M % 128 == 0, K % 8 == 0, N % 4 == 0 (N may be non-multiple of 128).
template <bool TRANSB, bool VSQ>
__global__ __launch_bounds__(256)
void gemm_kernel(const float* __restrict__ A, const float* __restrict__ B,
                 const float* __restrict__ bias, float* __restrict__ C,
                 int M, int N, int K,
                 size_t sA, size_t sB, size_t sC, int ldc) {
    __shared__ float As[8][132];
    __shared__ float Bs[8][132];
    const int bz = blockIdx.z;
    A += sA * bz;
    B += sB * bz;
    C += sC * bz;
    const int brow = blockIdx.y * 128;
    const int bcol = blockIdx.x * 128;
    const int t  = threadIdx.x;
    const int tx = t & 15;          // output col group
    const int ty = t >> 4;          // output row group
    const int lr  = t >> 1;         // 0..127 tile row for A (and B-rows if TRANSB)
    const int lk4 = (t & 1) * 4;    // 0 or 4
    const int bkr = t >> 5;         // 0..7   (NN B k-row)
    const int bnc = (t & 31) * 4;   // 0..124 (NN B n-col)

    float acc[8][8];
#pragma unroll
    for (int i = 0; i < 8; i++)
#pragma unroll
        for (int j = 0; j < 8; j++) acc[i][j] = 0.f;

    for (int k0 = 0; k0 < K; k0 += 8) {
        // A tile 128x8 -> As[k][m]  (transposed store, padded stride kills conflicts)
        float4 av = *reinterpret_cast<const float4*>(A + (size_t)(brow + lr) * K + (k0 + lk4));
        As[lk4 + 0][lr] = av.x;
        As[lk4 + 1][lr] = av.y;
        As[lk4 + 2][lr] = av.z;
        As[lk4 + 3][lr] = av.w;
        if (TRANSB) {
            const int nr = bcol + lr;
            float4 bv = make_float4(0.f, 0.f, 0.f, 0.f);
            if (nr < N) bv = *reinterpret_cast<const float4*>(B + (size_t)nr * K + (k0 + lk4));
            Bs[lk4 + 0][lr] = bv.x;
            Bs[lk4 + 1][lr] = bv.y;
            Bs[lk4 + 2][lr] = bv.z;
            Bs[lk4 + 3][lr] = bv.w;
        } else {
            const int nc = bcol + bnc;
            float4 bv = make_float4(0.f, 0.f, 0.f, 0.f);
            if (nc < N) bv = *reinterpret_cast<const float4*>(B + (size_t)(k0 + bkr) * N + nc);
            *reinterpret_cast<float4*>(&Bs[bkr][bnc]) = bv;
        }
        __syncthreads();
#pragma unroll
        for (int kk = 0; kk < 8; kk++) {
            float ar[8], br[8];
            *reinterpret_cast<float4*>(ar)     = *reinterpret_cast<const float4*>(&As[kk][ty * 8]);
            *reinterpret_cast<float4*>(ar + 4) = *reinterpret_cast<const float4*>(&As[kk][ty * 8 + 4]);
            *reinterpret_cast<float4*>(br)     = *reinterpret_cast<const float4*>(&Bs[kk][tx * 8]);
            *reinterpret_cast<float4*>(br + 4) = *reinterpret_cast<const float4*>(&Bs[kk][tx * 8 + 4]);
#pragma unroll
            for (int i = 0; i < 8; i++)
#pragma unroll
                for (int j = 0; j < 8; j++) acc[i][j] = fmaf(ar[i], br[j], acc[i][j]);
        }
        __syncthreads();
    }

#pragma unroll
    for (int i = 0; i < 8; i++) {
        const int row = brow + ty * 8 + i;
#pragma unroll
        for (int j = 0; j < 8; j++) {
            const int col = bcol + tx * 8 + j;
            if (col < N) {
                float v = acc[i][j];
                if (bias) v += bias[col];
                C[(size_t)row * ldc + col] = v;
                if (VSQ) C[(size_t)row * ldc + (ldc >> 1) + col] = v * v;
            }
        }
    }
}

// ---------------- row softmax (4096-wide rows, one block/row) ----------------
__global__ __launch_bounds__(256)
void softmax_kernel(float* __restrict__ A) {
    float* p = A + (size_t)blockIdx.x * NPIX;
    const int t = threadIdx.x;
    float v[16];
    float mx = -3.0e38f;
#pragma unroll
    for (int i = 0; i < 16; i++) {
        v[i] = p[t + 256 * i];
        mx = fmaxf(mx, v[i]);
    }
    __shared__ float red[8];
#pragma unroll
    for (int o = 16; o > 0; o >>= 1) mx = fmaxf(mx, __shfl_xor_sync(0xffffffffu, mx, o));
    if ((t & 31) == 0) red[t >> 5] = mx;
    __syncthreads();
    mx = red[0];
#pragma unroll
    for (int w = 1; w < 8; w++) mx = fmaxf(mx, red[w]);

    float s = 0.f;
#pragma unroll
    for (int i = 0; i < 16; i++) {
        v[i] = __expf(v[i] - mx);
        s += v[i];
    }
#pragma unroll
    for (int o = 16; o > 0; o >>= 1) s += __shfl_xor_sync(0xffffffffu, s, o);
    __syncthreads();               // all reads of red (max) done before reuse
    if ((t & 31) == 0) red[t >> 5] = s;
    __syncthreads();
    s = red[0];
#pragma unroll
    for (int w = 1; w < 8; w++) s += red[w];
    const float inv = 1.f / s;
#pragma unroll
    for (int i = 0; i < 16; i++) p[t + 256 * i] = v[i] * inv;
}

// ---------------- epilogue: out = sqrt(max(E2 - M^2, 1e-9)) * inorm(content) + M ----------------
__global__ __launch_bounds__(256)
void epilogue_kernel(const float* __restrict__ content, float* __restrict__ out) {
    size_t i4 = ((size_t)blockIdx.x * 256 + threadIdx.x) * 4;
    const size_t total = (size_t)BB * NPIX * C0;
    if (i4 >= total) return;
    int c = (int)(i4 % C0);
    size_t bn = i4 / C0;
    int b = (int)(bn >> 12);                              // bn / 4096
    float4 m4 = *reinterpret_cast<const float4*>(g_MV + bn * NVV + c);
    float4 e4 = *reinterpret_cast<const float4*>(g_MV + bn * NVV + C0 + c);
    float4 x4 = *reinterpret_cast<const float4*>(content + i4);
    const float* meanp = g_norms + b * C0 + c;            // content mean
    const float* rstdp = g_norms + BB * C0 + b * C0 + c;  // content rstd
    float4 o;
    {
        float s = sqrtf(fmaxf(e4.x - m4.x * m4.x, 1e-9f));
        o.x = s * ((x4.x - meanp[0]) * rstdp[0]) + m4.x;
    }
    {
        float s = sqrtf(fmaxf(e4.y - m4.y * m4.y, 1e-9f));
        o.y = s * ((x4.y - meanp[1]) * rstdp[1]) + m4.y;
    }
    {
        float s = sqrtf(fmaxf(e4.z - m4.z * m4.z, 1e-9f));
        o.z = s * ((x4.z - meanp[2]) * rstdp[2]) + m4.z;
    }
    {
        float s = sqrtf(fmaxf(e4.w - m4.w * m4.w, 1e-9f));
        o.w = s * ((x4.w - meanp[3]) * rstdp[3]) + m4.w;
    }
    *reinterpret_cast<float4*>(out + i4) = o;
}

// ---------------- launch ----------------
extern "C" void kernel_launch(void* const* d_in, const int* in_sizes, int n_in,
                              void* d_out, int out_size) {
    (void)in_sizes; (void)n_in; (void)out_size;
    const float* content   = (const float*)d_in[0];
    const float* style     = (const float*)d_in[1];
    const float* comb_cont = (const float*)d_in[2];
    const float* comb_sty  = (const float*)d_in[3];
    const float* Wq = (const float*)d_in[4];
    const float* bq = (const float*)d_in[5];
    const float* Wk = (const float*)d_in[6];
    const float* bk = (const float*)d_in[7];
    const float* Wv = (const float*)d_in[8];
    const float* bv = (const float*)d_in[9];
    float* out = (float*)d_out;

    float *Xqn, *Xkn, *Qp, *Kp, *VVp, *Ap, *MVp, *sums, *norms;
    cudaGetSymbolAddress((void**)&Xqn,   g_Xqn);
    cudaGetSymbolAddress((void**)&Xkn,   g_Xkn);
    cudaGetSymbolAddress((void**)&Qp,    g_Q);
    cudaGetSymbolAddress((void**)&Kp,    g_Kk);
    cudaGetSymbolAddress((void**)&VVp,   g_VV);
    cudaGetSymbolAddress((void**)&Ap,    g_A);
    cudaGetSymbolAddress((void**)&MVp,   g_MV);
    cudaGetSymbolAddress((void**)&sums,  g_sums);
    cudaGetSymbolAddress((void**)&norms, g_norms);

    // 1) instance-norm statistics for content / comb_cont / comb_sty
    zero_kernel<<<(NSTAT + 255) / 256, 256>>>(sums, NSTAT);
    stats_partial<<<dim3(4, 32, BB), 128>>>(content,   sums,                             sums + BB * C0,                   C0);
    stats_partial<<<dim3(8, 32, BB), 128>>>(comb_cont, sums + 2 * BB * C0,               sums + 2 * BB * C0 + BB * C1,     C1);
    stats_partial<<<dim3(8, 32, BB), 128>>>(comb_sty,  sums + 2 * BB * C0 + 2 * BB * C1, sums + 2 * BB * C0 + 3 * BB * C1, C1);
    stats_finalize_kernel<<<(BB * C0 + 2 * BB * C1 + 255) / 256, 256>>>();

    // 2) normalize the comb tensors
    const int nrm_blocks = (int)(((size_t)BB * NPIX * C1 / 4 + 255) / 256);
    normalize_kernel<<<nrm_blocks, 256>>>(comb_cont, Xqn, norms + 2 * BB * C0,               norms + 2 * BB * C0 + BB * C1);
    normalize_kernel<<<nrm_blocks, 256>>>(comb_sty,  Xkn, norms + 2 * BB * C0 + 2 * BB * C1, norms + 2 * BB * C0 + 3 * BB * C1);

    // 3) projections: Q, K (C1 x C1), V (+V^2 fused) (C0 x C0)
    gemm_kernel<false, false><<<dim3(8, 32, BB), 256>>>(Xqn, Wq, bq, Qp, NPIX, C1, C1,
                                                        (size_t)NPIX * C1, 0, (size_t)NPIX * C1, C1);
    gemm_kernel<false, false><<<dim3(8, 32, BB), 256>>>(Xkn, Wk, bk, Kp, NPIX, C1, C1,
                                                        (size_t)NPIX * C1, 0, (size_t)NPIX * C1, C1);
    gemm_kernel<false, true ><<<dim3(4, 32, BB), 256>>>(style, Wv, bv, VVp, NPIX, C0, C0,
                                                        (size_t)NPIX * C0, 0, (size_t)NPIX * NVV, NVV);

    // 4) logits = Q @ K^T  (NT GEMM), then row softmax
    gemm_kernel<true, false><<<dim3(32, 32, BB), 256>>>(Qp, Kp, nullptr, Ap, NPIX, NPIX, C1,
                                                        (size_t)NPIX * C1, (size_t)NPIX * C1,
                                                        (size_t)NPIX * NPIX, NPIX);
    softmax_kernel<<<BB * NPIX, 256>>>(Ap);

    // 5) [M | E2] = A @ [V | V^2]   (single pass over A)
    gemm_kernel<false, false><<<dim3(8, 32, BB), 256>>>(Ap, VVp, nullptr, MVp, NPIX, NVV, NPIX,
                                                        (size_t)NPIX * NPIX, (size_t)NPIX * NVV,
                                                        (size_t)NPIX * NVV, NVV);

    // 6) out = S * inorm(content) + M
    epilogue_kernel<<<(int)(((size_t)BB * NPIX * C0 / 4 + 255) / 256), 256>>>(content, out);
}

// round 2
// speedup vs baseline: 1.7410x; 1.7410x over previous
#include <cuda_runtime.h>
#include <cuda_bf16.h>
#include <cstdint>
#include <cstddef>

// Problem constants (fixed shapes from reference)
#define BB   4
#define NPIX 4096      // H*W = 64*64
#define C0   512       // content / V channels
#define C1   960       // comb channels
#define NVV  1024      // [V | V*V] concatenated width

// ---------------- scratch (device globals; no allocation allowed) ----------------
static __device__ float g_Xqn[(size_t)BB * NPIX * C1];   // normalized comb_cont
static __device__ float g_Xkn[(size_t)BB * NPIX * C1];   // normalized comb_sty; later reused as K^T
static __device__ float g_Q  [(size_t)BB * NPIX * C1];
static __device__ float g_Kk [(size_t)BB * NPIX * C1];
static __device__ float g_VV [(size_t)BB * NPIX * NVV];  // [V | V^2]
static __device__ float g_A  [(size_t)BB * NPIX * NPIX]; // attention (268 MB)
static __device__ float g_MV [(size_t)BB * NPIX * NVV];  // [M | E2]

#define NSTAT (2 * BB * C0 + 4 * BB * C1)   // 19456
static __device__ float g_sums [NSTAT];
static __device__ float g_norms[NSTAT];

// ---------------- small kernels ----------------

__global__ void zero_kernel(float* __restrict__ p, int n) {
    int i = blockIdx.x * 256 + threadIdx.x;
    if (i < n) p[i] = 0.f;
}

// Per-(b,channel) partial sums over a 128-row spatial chunk; atomically combined.
__global__ __launch_bounds__(128)
void stats_partial(const float* __restrict__ X, float* __restrict__ sum,
                   float* __restrict__ ssq, int Cx) {
    const int c = blockIdx.x * 128 + threadIdx.x;
    if (c >= Cx) return;
    const int b = blockIdx.z;
    const int chunk = blockIdx.y;                    // 32 chunks of 128 rows
    const float* p = X + ((size_t)b * NPIX + (size_t)chunk * 128) * Cx + c;
    float s = 0.f, s2 = 0.f;
#pragma unroll 8
    for (int n = 0; n < 128; n++) {
        float x = p[(size_t)n * Cx];
        s += x;
        s2 = fmaf(x, x, s2);
    }
    atomicAdd(&sum[b * Cx + c], s);
    atomicAdd(&ssq[b * Cx + c], s2);
}

__global__ void stats_finalize_kernel() {
    const int nch = BB * C0 + 2 * BB * C1;           // 9728
    int i = blockIdx.x * 256 + threadIdx.x;
    if (i >= nch) return;
    int sum_idx, ssq_idx;
    if (i < BB * C0) {
        sum_idx = i;
        ssq_idx = BB * C0 + i;
    } else if (i < BB * C0 + BB * C1) {
        int j = i - BB * C0;
        sum_idx = 2 * BB * C0 + j;
        ssq_idx = 2 * BB * C0 + BB * C1 + j;
    } else {
        int j = i - BB * C0 - BB * C1;
        sum_idx = 2 * BB * C0 + 2 * BB * C1 + j;
        ssq_idx = sum_idx + BB * C1;
    }
    float m   = g_sums[sum_idx] * (1.f / NPIX);
    float var = g_sums[ssq_idx] * (1.f / NPIX) - m * m;
    g_norms[sum_idx] = m;
    g_norms[ssq_idx] = rsqrtf(var + 1e-5f);
}

// Elementwise instance-norm apply (C1-wide tensors), float4 vectorized (C1 % 4 == 0).
__global__ __launch_bounds__(256)
void normalize_kernel(const float* __restrict__ X, float* __restrict__ Y,
                      const float* __restrict__ mean, const float* __restrict__ rstd) {
    size_t i4 = ((size_t)blockIdx.x * 256 + threadIdx.x) * 4;
    const size_t total = (size_t)BB * NPIX * C1;
    if (i4 >= total) return;
    int c = (int)(i4 % C1);
    int b = (int)(i4 / ((size_t)NPIX * C1));
    float4 x = *reinterpret_cast<const float4*>(X + i4);
    const float* mp = mean + b * C1 + c;
    const float* rp = rstd + b * C1 + c;
    float4 y;
    y.x = (x.x - mp[0]) * rp[0];
    y.y = (x.y - mp[1]) * rp[1];
    y.z = (x.z - mp[2]) * rp[2];
    y.w = (x.w - mp[3]) * rp[3];
    *reinterpret_cast<float4*>(Y + i4) = y;
}

// 32x32 tiled transpose: src [NPIX][C1] -> dst [C1][NPIX] per batch.
__global__ __launch_bounds__(256)
void transpose_kernel(const float* __restrict__ src, float* __restrict__ dst) {
    __shared__ float tile[32][33];
    const int b = blockIdx.z;
    src += (size_t)b * NPIX * C1;
    dst += (size_t)b * NPIX * C1;
    int x = blockIdx.x * 32 + threadIdx.x;   // C1 index
    int y = blockIdx.y * 32 + threadIdx.y;   // NPIX index
#pragma unroll
    for (int j = 0; j < 32; j += 8)
        tile[threadIdx.y + j][threadIdx.x] = src[(size_t)(y + j) * C1 + x];
    __syncthreads();
    x = blockIdx.y * 32 + threadIdx.x;       // NPIX index
    y = blockIdx.x * 32 + threadIdx.y;       // C1 index
#pragma unroll
    for (int j = 0; j < 32; j += 8)
        dst[(size_t)(y + j) * NPIX + x] = tile[threadIdx.x][threadIdx.y + j];
}

// ---------------- tensor-core GEMM: bf16x3 split precision ----------------
// C[m,n] = sum_k A[m,k] * B[k,n], all fp32 in gmem; internally each operand is
// split x = hi + lo (bf16 each) and accumulated as hi*hi + hi*lo + lo*hi in fp32
// via mma.sync.m16n8k16 — error ~2^-16 per product (fp32-class for this problem).
// Block tile 128x128x32, 8 warps (2x4), warp tile 64x32, 16 mma frags/warp.
// Requirements: M % 128 == 0, K % 32 == 0, N % 4 == 0, ld(B) == N.

__device__ __forceinline__ uint32_t saddr(const void* p) {
    return (uint32_t)__cvta_generic_to_shared(p);
}
__device__ __forceinline__ void ldsm_x4(uint32_t* r, uint32_t a) {
    asm volatile("ldmatrix.sync.aligned.m8n8.x4.shared.b16 {%0,%1,%2,%3}, [%4];"
                 : "=r"(r[0]), "=r"(r[1]), "=r"(r[2]), "=r"(r[3]) : "r"(a));
}
__device__ __forceinline__ void ldsm_x4t(uint32_t* r, uint32_t a) {
    asm volatile("ldmatrix.sync.aligned.m8n8.x4.trans.shared.b16 {%0,%1,%2,%3}, [%4];"
                 : "=r"(r[0]), "=r"(r[1]), "=r"(r[2]), "=r"(r[3]) : "r"(a));
}
__device__ __forceinline__ void mma_bf16(float* d, const uint32_t* a, const uint32_t* b) {
    asm volatile(
        "mma.sync.aligned.m16n8k16.row.col.f32.bf16.bf16.f32 "
        "{%0,%1,%2,%3}, {%4,%5,%6,%7}, {%8,%9}, {%0,%1,%2,%3};"
        : "+f"(d[0]), "+f"(d[1]), "+f"(d[2]), "+f"(d[3])
        : "r"(a[0]), "r"(a[1]), "r"(a[2]), "r"(a[3]), "r"(b[0]), "r"(b[1]));
}
__device__ __forceinline__ uint32_t pack_bf2(__nv_bfloat16 x, __nv_bfloat16 y) {
    return ((uint32_t)__bfloat16_as_ushort(y) << 16) | (uint32_t)__bfloat16_as_ushort(x);
}

#define BKP 40     // A smem row stride (elems): 80B, ldmatrix conflict-free
#define BNP 136    // B smem row stride (elems): 272B, ldmatrix conflict-free

template <bool VSQ>
__global__ __launch_bounds__(256)
void mma_gemm(const float* __restrict__ A, const float* __restrict__ B,
              const float* __restrict__ bias, float* __restrict__ C,
              int M, int N, int K,
              size_t sA, size_t sB, size_t sC, int ldc) {
    __shared__ __nv_bfloat16 As[2][128][BKP];   // [hi/lo][m][k]
    __shared__ __nv_bfloat16 Bs[2][32][BNP];    // [hi/lo][k][n]

    const int bz = blockIdx.z;
    A += sA * bz;
    B += sB * bz;
    C += sC * bz;
    const int brow = blockIdx.y * 128;
    const int bcol = blockIdx.x * 128;
    const int t    = threadIdx.x;
    const int lane = t & 31;
    const int wid  = t >> 5;
    const int wm   = wid & 1;       // warp row group (64 rows)
    const int wn   = wid >> 1;      // warp col group (32 cols)

    const int a_kq = t & 7;         // float4 index along k for A loads
    const int a_m  = t >> 3;        // 0..31, step 32 over 4 passes
    const int b_n4 = t & 31;        // float4 index along n for B loads
    const int b_k  = t >> 5;        // 0..7, step 8 over 4 passes

    float acc[4][4][4];
#pragma unroll
    for (int mi = 0; mi < 4; mi++)
#pragma unroll
        for (int ni = 0; ni < 4; ni++)
#pragma unroll
            for (int r = 0; r < 4; r++) acc[mi][ni][r] = 0.f;

    for (int k0 = 0; k0 < K; k0 += 32) {
        // ---- A tile: 128 rows x 32 k (fp32) -> hi/lo bf16 planes ----
#pragma unroll
        for (int p = 0; p < 4; p++) {
            const int m = a_m + p * 32;
            float4 v = *reinterpret_cast<const float4*>(
                A + (size_t)(brow + m) * K + k0 + a_kq * 4);
            float f[4] = {v.x, v.y, v.z, v.w};
            __nv_bfloat16 h[4], l[4];
#pragma unroll
            for (int i = 0; i < 4; i++) {
                h[i] = __float2bfloat16(f[i]);
                l[i] = __float2bfloat16(f[i] - __bfloat162float(h[i]));
            }
            uint2 uh, ul;
            uh.x = pack_bf2(h[0], h[1]); uh.y = pack_bf2(h[2], h[3]);
            ul.x = pack_bf2(l[0], l[1]); ul.y = pack_bf2(l[2], l[3]);
            *reinterpret_cast<uint2*>(&As[0][m][a_kq * 4]) = uh;
            *reinterpret_cast<uint2*>(&As[1][m][a_kq * 4]) = ul;
        }
        // ---- B tile: 32 k-rows x 128 n (fp32, ld == N) -> hi/lo planes ----
#pragma unroll
        for (int p = 0; p < 4; p++) {
            const int kk = b_k + p * 8;
            const int n4 = bcol + b_n4 * 4;
            float4 v = make_float4(0.f, 0.f, 0.f, 0.f);
            if (n4 < N)
                v = *reinterpret_cast<const float4*>(B + (size_t)(k0 + kk) * N + n4);
            float f[4] = {v.x, v.y, v.z, v.w};
            __nv_bfloat16 h[4], l[4];
#pragma unroll
            for (int i = 0; i < 4; i++) {
                h[i] = __float2bfloat16(f[i]);
                l[i] = __float2bfloat16(f[i] - __bfloat162float(h[i]));
            }
            uint2 uh, ul;
            uh.x = pack_bf2(h[0], h[1]); uh.y = pack_bf2(h[2], h[3]);
            ul.x = pack_bf2(l[0], l[1]); ul.y = pack_bf2(l[2], l[3]);
            *reinterpret_cast<uint2*>(&Bs[0][kk][b_n4 * 4]) = uh;
            *reinterpret_cast<uint2*>(&Bs[1][kk][b_n4 * 4]) = ul;
        }
        __syncthreads();

#pragma unroll
        for (int ks = 0; ks < 32; ks += 16) {
            uint32_t ah[4][4], al[4][4], bh[4][2], bl[4][2];
            // A fragments (row-major 16x16 via ldmatrix.x4)
#pragma unroll
            for (int mi = 0; mi < 4; mi++) {
                const int r  = wm * 64 + mi * 16 + (lane & 15);
                const int kc = ks + ((lane >> 4) << 3);
                ldsm_x4(ah[mi], saddr(&As[0][r][kc]));
                ldsm_x4(al[mi], saddr(&As[1][r][kc]));
            }
            // B fragments (k-major via ldmatrix.x4.trans; 2 n8-tiles per instr)
#pragma unroll
            for (int g = 0; g < 2; g++) {
                const int kr = ks + (lane & 7) + (((lane >> 3) & 1) << 3);
                const int nn = wn * 32 + g * 16 + (((lane >> 4) & 1) << 3);
                uint32_t tmp[4];
                ldsm_x4t(tmp, saddr(&Bs[0][kr][nn]));
                bh[g * 2 + 0][0] = tmp[0]; bh[g * 2 + 0][1] = tmp[1];
                bh[g * 2 + 1][0] = tmp[2]; bh[g * 2 + 1][1] = tmp[3];
                ldsm_x4t(tmp, saddr(&Bs[1][kr][nn]));
                bl[g * 2 + 0][0] = tmp[0]; bl[g * 2 + 0][1] = tmp[1];
                bl[g * 2 + 1][0] = tmp[2]; bl[g * 2 + 1][1] = tmp[3];
            }
            // 3-pass split-precision accumulate
#pragma unroll
            for (int mi = 0; mi < 4; mi++)
#pragma unroll
                for (int ni = 0; ni < 4; ni++) {
                    mma_bf16(acc[mi][ni], ah[mi], bh[ni]);
                    mma_bf16(acc[mi][ni], ah[mi], bl[ni]);
                    mma_bf16(acc[mi][ni], al[mi], bh[ni]);
                }
        }
        __syncthreads();
    }

    // ---- epilogue ----
#pragma unroll
    for (int mi = 0; mi < 4; mi++) {
        const int r0 = brow + wm * 64 + mi * 16 + (lane >> 2);
#pragma unroll
        for (int ni = 0; ni < 4; ni++) {
            const int c0 = bcol + wn * 32 + ni * 8 + (lane & 3) * 2;
            if (c0 < N) {
                const float b0 = bias ? bias[c0] : 0.f;
                const float b1 = bias ? bias[c0 + 1] : 0.f;
                const float* a = acc[mi][ni];
                const float v00 = a[0] + b0, v01 = a[1] + b1;
                const float v10 = a[2] + b0, v11 = a[3] + b1;
                C[(size_t)r0 * ldc + c0]           = v00;
                C[(size_t)r0 * ldc + c0 + 1]       = v01;
                C[(size_t)(r0 + 8) * ldc + c0]     = v10;
                C[(size_t)(r0 + 8) * ldc + c0 + 1] = v11;
                if (VSQ) {
                    const int h = ldc >> 1;
                    C[(size_t)r0 * ldc + h + c0]           = v00 * v00;
                    C[(size_t)r0 * ldc + h + c0 + 1]       = v01 * v01;
                    C[(size_t)(r0 + 8) * ldc + h + c0]     = v10 * v10;
                    C[(size_t)(r0 + 8) * ldc + h + c0 + 1] = v11 * v11;
                }
            }
        }
    }
}

// ---------------- row softmax (4096-wide rows, one block/row) ----------------
__global__ __launch_bounds__(256)
void softmax_kernel(float* __restrict__ A) {
    float* p = A + (size_t)blockIdx.x * NPIX;
    const int t = threadIdx.x;
    float v[16];
    float mx = -3.0e38f;
#pragma unroll
    for (int i = 0; i < 16; i++) {
        v[i] = p[t + 256 * i];
        mx = fmaxf(mx, v[i]);
    }
    __shared__ float red[8];
#pragma unroll
    for (int o = 16; o > 0; o >>= 1) mx = fmaxf(mx, __shfl_xor_sync(0xffffffffu, mx, o));
    if ((t & 31) == 0) red[t >> 5] = mx;
    __syncthreads();
    mx = red[0];
#pragma unroll
    for (int w = 1; w < 8; w++) mx = fmaxf(mx, red[w]);

    float s = 0.f;
#pragma unroll
    for (int i = 0; i < 16; i++) {
        v[i] = __expf(v[i] - mx);
        s += v[i];
    }
#pragma unroll
    for (int o = 16; o > 0; o >>= 1) s += __shfl_xor_sync(0xffffffffu, s, o);
    __syncthreads();
    if ((t & 31) == 0) red[t >> 5] = s;
    __syncthreads();
    s = red[0];
#pragma unroll
    for (int w = 1; w < 8; w++) s += red[w];
    const float inv = 1.f / s;
#pragma unroll
    for (int i = 0; i < 16; i++) p[t + 256 * i] = v[i] * inv;
}

// ---------------- epilogue: out = sqrt(max(E2 - M^2, 1e-9)) * inorm(content) + M ----------------
__global__ __launch_bounds__(256)
void epilogue_kernel(const float* __restrict__ content, float* __restrict__ out) {
    size_t i4 = ((size_t)blockIdx.x * 256 + threadIdx.x) * 4;
    const size_t total = (size_t)BB * NPIX * C0;
    if (i4 >= total) return;
    int c = (int)(i4 % C0);
    size_t bn = i4 / C0;
    int b = (int)(bn >> 12);
    float4 m4 = *reinterpret_cast<const float4*>(g_MV + bn * NVV + c);
    float4 e4 = *reinterpret_cast<const float4*>(g_MV + bn * NVV + C0 + c);
    float4 x4 = *reinterpret_cast<const float4*>(content + i4);
    const float* meanp = g_norms + b * C0 + c;
    const float* rstdp = g_norms + BB * C0 + b * C0 + c;
    float4 o;
    o.x = sqrtf(fmaxf(e4.x - m4.x * m4.x, 1e-9f)) * ((x4.x - meanp[0]) * rstdp[0]) + m4.x;
    o.y = sqrtf(fmaxf(e4.y - m4.y * m4.y, 1e-9f)) * ((x4.y - meanp[1]) * rstdp[1]) + m4.y;
    o.z = sqrtf(fmaxf(e4.z - m4.z * m4.z, 1e-9f)) * ((x4.z - meanp[2]) * rstdp[2]) + m4.z;
    o.w = sqrtf(fmaxf(e4.w - m4.w * m4.w, 1e-9f)) * ((x4.w - meanp[3]) * rstdp[3]) + m4.w;
    *reinterpret_cast<float4*>(out + i4) = o;
}

// ---------------- launch ----------------
extern "C" void kernel_launch(void* const* d_in, const int* in_sizes, int n_in,
                              void* d_out, int out_size) {
    (void)in_sizes; (void)n_in; (void)out_size;
    const float* content   = (const float*)d_in[0];
    const float* style     = (const float*)d_in[1];
    const float* comb_cont = (const float*)d_in[2];
    const float* comb_sty  = (const float*)d_in[3];
    const float* Wq = (const float*)d_in[4];
    const float* bq = (const float*)d_in[5];
    const float* Wk = (const float*)d_in[6];
    const float* bk = (const float*)d_in[7];
    const float* Wv = (const float*)d_in[8];
    const float* bv = (const float*)d_in[9];
    float* out = (float*)d_out;

    float *Xqn, *Xkn, *Qp, *Kp, *VVp, *Ap, *MVp, *sums, *norms;
    cudaGetSymbolAddress((void**)&Xqn,   g_Xqn);
    cudaGetSymbolAddress((void**)&Xkn,   g_Xkn);
    cudaGetSymbolAddress((void**)&Qp,    g_Q);
    cudaGetSymbolAddress((void**)&Kp,    g_Kk);
    cudaGetSymbolAddress((void**)&VVp,   g_VV);
    cudaGetSymbolAddress((void**)&Ap,    g_A);
    cudaGetSymbolAddress((void**)&MVp,   g_MV);
    cudaGetSymbolAddress((void**)&sums,  g_sums);
    cudaGetSymbolAddress((void**)&norms, g_norms);

    // 1) instance-norm statistics for content / comb_cont / comb_sty
    zero_kernel<<<(NSTAT + 255) / 256, 256>>>(sums, NSTAT);
    stats_partial<<<dim3(4, 32, BB), 128>>>(content,   sums,                             sums + BB * C0,                   C0);
    stats_partial<<<dim3(8, 32, BB), 128>>>(comb_cont, sums + 2 * BB * C0,               sums + 2 * BB * C0 + BB * C1,     C1);
    stats_partial<<<dim3(8, 32, BB), 128>>>(comb_sty,  sums + 2 * BB * C0 + 2 * BB * C1, sums + 2 * BB * C0 + 3 * BB * C1, C1);
    stats_finalize_kernel<<<(BB * C0 + 2 * BB * C1 + 255) / 256, 256>>>();

    // 2) normalize the comb tensors
    const int nrm_blocks = (int)(((size_t)BB * NPIX * C1 / 4 + 255) / 256);
    normalize_kernel<<<nrm_blocks, 256>>>(comb_cont, Xqn, norms + 2 * BB * C0,               norms + 2 * BB * C0 + BB * C1);
    normalize_kernel<<<nrm_blocks, 256>>>(comb_sty,  Xkn, norms + 2 * BB * C0 + 2 * BB * C1, norms + 2 * BB * C0 + 3 * BB * C1);

    // 3) projections (tensor-core bf16x3): Q, K (4096x960x960), V+V^2 (4096x512x512)
    mma_gemm<false><<<dim3(8, 32, BB), 256>>>(Xqn,  Wq, bq, Qp,  NPIX, C1, C1,
                                              (size_t)NPIX * C1, 0, (size_t)NPIX * C1, C1);
    mma_gemm<false><<<dim3(8, 32, BB), 256>>>(Xkn,  Wk, bk, Kp,  NPIX, C1, C1,
                                              (size_t)NPIX * C1, 0, (size_t)NPIX * C1, C1);
    mma_gemm<true ><<<dim3(4, 32, BB), 256>>>(style, Wv, bv, VVp, NPIX, C0, C0,
                                              (size_t)NPIX * C0, 0, (size_t)NPIX * NVV, NVV);

    // 3b) K -> K^T  (so logits GEMM is NN); Xkn buffer is free now, reuse as Kt
    transpose_kernel<<<dim3(C1 / 32, NPIX / 32, BB), dim3(32, 8)>>>(Kp, Xkn);

    // 4) logits = Q @ K^T  (4096x4096x960), then row softmax
    mma_gemm<false><<<dim3(32, 32, BB), 256>>>(Qp, Xkn, nullptr, Ap, NPIX, NPIX, C1,
                                               (size_t)NPIX * C1, (size_t)NPIX * C1,
                                               (size_t)NPIX * NPIX, NPIX);
    softmax_kernel<<<BB * NPIX, 256>>>(Ap);

    // 5) [M | E2] = A @ [V | V^2]   (4096x1024x4096, single pass over A)
    mma_gemm<false><<<dim3(8, 32, BB), 256>>>(Ap, VVp, nullptr, MVp, NPIX, NVV, NPIX,
                                              (size_t)NPIX * NPIX, (size_t)NPIX * NVV,
                                              (size_t)NPIX * NVV, NVV);

    // 6) out = S * inorm(content) + M
    epilogue_kernel<<<(int)(((size_t)BB * NPIX * C0 / 4 + 255) / 256), 256>>>(content, out);
}

// round 3
// speedup vs baseline: 1.7554x; 1.0083x over previous
#include <cuda_runtime.h>
#include <cuda_bf16.h>
#include <cstdint>
#include <cstddef>

// Problem constants (fixed shapes from reference)
#define BB   4
#define NPIX 4096      // H*W = 64*64
#define C0   512       // content / V channels
#define C1   960       // comb channels
#define NVV  1024      // [V | V*V] concatenated width

// ---------------- scratch (device globals; no allocation allowed) ----------------
static __device__ float g_Xqn[(size_t)BB * NPIX * C1];   // normalized comb_cont
static __device__ float g_Xkn[(size_t)BB * NPIX * C1];   // normalized comb_sty; later reused as K^T
static __device__ float g_Q  [(size_t)BB * NPIX * C1];
static __device__ float g_Kk [(size_t)BB * NPIX * C1];
static __device__ float g_VV [(size_t)BB * NPIX * NVV];  // [V | V^2]
static __device__ float g_A  [(size_t)BB * NPIX * NPIX]; // attention (268 MB)
static __device__ float g_MV [(size_t)BB * NPIX * NVV];  // [M | E2]

#define NSTAT (2 * BB * C0 + 4 * BB * C1)   // 19456
static __device__ float g_sums [NSTAT];
static __device__ float g_norms[NSTAT];

// ---------------- small kernels ----------------

__global__ void zero_kernel(float* __restrict__ p, int n) {
    int i = blockIdx.x * 256 + threadIdx.x;
    if (i < n) p[i] = 0.f;
}

// Per-(b,channel) partial sums over a 128-row spatial chunk; atomically combined.
__global__ __launch_bounds__(128)
void stats_partial(const float* __restrict__ X, float* __restrict__ sum,
                   float* __restrict__ ssq, int Cx) {
    const int c = blockIdx.x * 128 + threadIdx.x;
    if (c >= Cx) return;
    const int b = blockIdx.z;
    const int chunk = blockIdx.y;                    // 32 chunks of 128 rows
    const float* p = X + ((size_t)b * NPIX + (size_t)chunk * 128) * Cx + c;
    float s = 0.f, s2 = 0.f;
#pragma unroll 8
    for (int n = 0; n < 128; n++) {
        float x = p[(size_t)n * Cx];
        s += x;
        s2 = fmaf(x, x, s2);
    }
    atomicAdd(&sum[b * Cx + c], s);
    atomicAdd(&ssq[b * Cx + c], s2);
}

__global__ void stats_finalize_kernel() {
    const int nch = BB * C0 + 2 * BB * C1;           // 9728
    int i = blockIdx.x * 256 + threadIdx.x;
    if (i >= nch) return;
    int sum_idx, ssq_idx;
    if (i < BB * C0) {
        sum_idx = i;
        ssq_idx = BB * C0 + i;
    } else if (i < BB * C0 + BB * C1) {
        int j = i - BB * C0;
        sum_idx = 2 * BB * C0 + j;
        ssq_idx = 2 * BB * C0 + BB * C1 + j;
    } else {
        int j = i - BB * C0 - BB * C1;
        sum_idx = 2 * BB * C0 + 2 * BB * C1 + j;
        ssq_idx = sum_idx + BB * C1;
    }
    float m   = g_sums[sum_idx] * (1.f / NPIX);
    float var = g_sums[ssq_idx] * (1.f / NPIX) - m * m;
    g_norms[sum_idx] = m;
    g_norms[ssq_idx] = rsqrtf(var + 1e-5f);
}

// Elementwise instance-norm apply (C1-wide tensors), float4 vectorized (C1 % 4 == 0).
__global__ __launch_bounds__(256)
void normalize_kernel(const float* __restrict__ X, float* __restrict__ Y,
                      const float* __restrict__ mean, const float* __restrict__ rstd) {
    size_t i4 = ((size_t)blockIdx.x * 256 + threadIdx.x) * 4;
    const size_t total = (size_t)BB * NPIX * C1;
    if (i4 >= total) return;
    int c = (int)(i4 % C1);
    int b = (int)(i4 / ((size_t)NPIX * C1));
    float4 x = *reinterpret_cast<const float4*>(X + i4);
    const float* mp = mean + b * C1 + c;
    const float* rp = rstd + b * C1 + c;
    float4 y;
    y.x = (x.x - mp[0]) * rp[0];
    y.y = (x.y - mp[1]) * rp[1];
    y.z = (x.z - mp[2]) * rp[2];
    y.w = (x.w - mp[3]) * rp[3];
    *reinterpret_cast<float4*>(Y + i4) = y;
}

// 32x32 tiled transpose: src [NPIX][C1] -> dst [C1][NPIX] per batch.
__global__ __launch_bounds__(256)
void transpose_kernel(const float* __restrict__ src, float* __restrict__ dst) {
    __shared__ float tile[32][33];
    const int b = blockIdx.z;
    src += (size_t)b * NPIX * C1;
    dst += (size_t)b * NPIX * C1;
    int x = blockIdx.x * 32 + threadIdx.x;   // C1 index
    int y = blockIdx.y * 32 + threadIdx.y;   // NPIX index
#pragma unroll
    for (int j = 0; j < 32; j += 8)
        tile[threadIdx.y + j][threadIdx.x] = src[(size_t)(y + j) * C1 + x];
    __syncthreads();
    x = blockIdx.y * 32 + threadIdx.x;       // NPIX index
    y = blockIdx.x * 32 + threadIdx.y;       // C1 index
#pragma unroll
    for (int j = 0; j < 32; j += 8)
        dst[(size_t)(y + j) * NPIX + x] = tile[threadIdx.x][threadIdx.y + j];
}

// ---------------- tensor-core GEMM: bf16x3 split precision ----------------
// C[m,n] = sum_k A[m,k] * B[k,n], all fp32 in gmem; internally each operand is
// split x = hi + lo (bf16 each) and accumulated as hi*hi + hi*lo + lo*hi in fp32
// via mma.sync.m16n8k16 — error ~2^-16 per product (fp32-class for this problem).
// Block tile 128x128x32, 8 warps (2x4), warp tile 64x32, 16 mma frags/warp.
// Requirements: M % 128 == 0, K % 32 == 0, N % 4 == 0, ld(B) == N.

__device__ __forceinline__ uint32_t saddr(const void* p) {
    return (uint32_t)__cvta_generic_to_shared(p);
}
__device__ __forceinline__ void ldsm_x4(uint32_t* r, uint32_t a) {
    asm volatile("ldmatrix.sync.aligned.m8n8.x4.shared.b16 {%0,%1,%2,%3}, [%4];"
                 : "=r"(r[0]), "=r"(r[1]), "=r"(r[2]), "=r"(r[3]) : "r"(a));
}
__device__ __forceinline__ void ldsm_x4t(uint32_t* r, uint32_t a) {
    asm volatile("ldmatrix.sync.aligned.m8n8.x4.trans.shared.b16 {%0,%1,%2,%3}, [%4];"
                 : "=r"(r[0]), "=r"(r[1]), "=r"(r[2]), "=r"(r[3]) : "r"(a));
}
__device__ __forceinline__ void mma_bf16(float* d, const uint32_t* a, const uint32_t* b) {
    asm volatile(
        "mma.sync.aligned.m16n8k16.row.col.f32.bf16.bf16.f32 "
        "{%0,%1,%2,%3}, {%4,%5,%6,%7}, {%8,%9}, {%0,%1,%2,%3};"
        : "+f"(d[0]), "+f"(d[1]), "+f"(d[2]), "+f"(d[3])
        : "r"(a[0]), "r"(a[1]), "r"(a[2]), "r"(a[3]), "r"(b[0]), "r"(b[1]));
}
__device__ __forceinline__ uint32_t pack_bf2(__nv_bfloat16 x, __nv_bfloat16 y) {
    return ((uint32_t)__bfloat16_as_ushort(y) << 16) | (uint32_t)__bfloat16_as_ushort(x);
}

#define BKP 40     // A smem row stride (elems): 80B, ldmatrix conflict-free
#define BNP 136    // B smem row stride (elems): 272B, ldmatrix conflict-free

template <bool VSQ>
__global__ __launch_bounds__(256)
void mma_gemm(const float* __restrict__ A, const float* __restrict__ B,
              const float* __restrict__ bias, float* __restrict__ C,
              int M, int N, int K,
              size_t sA, size_t sB, size_t sC, int ldc) {
    __shared__ __nv_bfloat16 As[2][128][BKP];   // [hi/lo][m][k]
    __shared__ __nv_bfloat16 Bs[2][32][BNP];    // [hi/lo][k][n]

    const int bz = blockIdx.z;
    A += sA * bz;
    B += sB * bz;
    C += sC * bz;
    const int brow = blockIdx.y * 128;
    const int bcol = blockIdx.x * 128;
    const int t    = threadIdx.x;
    const int lane = t & 31;
    const int wid  = t >> 5;
    const int wm   = wid & 1;       // warp row group (64 rows)
    const int wn   = wid >> 1;      // warp col group (32 cols)

    const int a_kq = t & 7;         // float4 index along k for A loads
    const int a_m  = t >> 3;        // 0..31, step 32 over 4 passes
    const int b_n4 = t & 31;        // float4 index along n for B loads
    const int b_k  = t >> 5;        // 0..7, step 8 over 4 passes

    float acc[4][4][4];
#pragma unroll
    for (int mi = 0; mi < 4; mi++)
#pragma unroll
        for (int ni = 0; ni < 4; ni++)
#pragma unroll
            for (int r = 0; r < 4; r++) acc[mi][ni][r] = 0.f;

    for (int k0 = 0; k0 < K; k0 += 32) {
        // ---- A tile: 128 rows x 32 k (fp32) -> hi/lo bf16 planes ----
#pragma unroll
        for (int p = 0; p < 4; p++) {
            const int m = a_m + p * 32;
            float4 v = *reinterpret_cast<const float4*>(
                A + (size_t)(brow + m) * K + k0 + a_kq * 4);
            float f[4] = {v.x, v.y, v.z, v.w};
            __nv_bfloat16 h[4], l[4];
#pragma unroll
            for (int i = 0; i < 4; i++) {
                h[i] = __float2bfloat16(f[i]);
                l[i] = __float2bfloat16(f[i] - __bfloat162float(h[i]));
            }
            uint2 uh, ul;
            uh.x = pack_bf2(h[0], h[1]); uh.y = pack_bf2(h[2], h[3]);
            ul.x = pack_bf2(l[0], l[1]); ul.y = pack_bf2(l[2], l[3]);
            *reinterpret_cast<uint2*>(&As[0][m][a_kq * 4]) = uh;
            *reinterpret_cast<uint2*>(&As[1][m][a_kq * 4]) = ul;
        }
        // ---- B tile: 32 k-rows x 128 n (fp32, ld == N) -> hi/lo planes ----
#pragma unroll
        for (int p = 0; p < 4; p++) {
            const int kk = b_k + p * 8;
            const int n4 = bcol + b_n4 * 4;
            float4 v = make_float4(0.f, 0.f, 0.f, 0.f);
            if (n4 < N)
                v = *reinterpret_cast<const float4*>(B + (size_t)(k0 + kk) * N + n4);
            float f[4] = {v.x, v.y, v.z, v.w};
            __nv_bfloat16 h[4], l[4];
#pragma unroll
            for (int i = 0; i < 4; i++) {
                h[i] = __float2bfloat16(f[i]);
                l[i] = __float2bfloat16(f[i] - __bfloat162float(h[i]));
            }
            uint2 uh, ul;
            uh.x = pack_bf2(h[0], h[1]); uh.y = pack_bf2(h[2], h[3]);
            ul.x = pack_bf2(l[0], l[1]); ul.y = pack_bf2(l[2], l[3]);
            *reinterpret_cast<uint2*>(&Bs[0][kk][b_n4 * 4]) = uh;
            *reinterpret_cast<uint2*>(&Bs[1][kk][b_n4 * 4]) = ul;
        }
        __syncthreads();

#pragma unroll
        for (int ks = 0; ks < 32; ks += 16) {
            uint32_t ah[4][4], al[4][4], bh[4][2], bl[4][2];
            // A fragments (row-major 16x16 via ldmatrix.x4)
#pragma unroll
            for (int mi = 0; mi < 4; mi++) {
                const int r  = wm * 64 + mi * 16 + (lane & 15);
                const int kc = ks + ((lane >> 4) << 3);
                ldsm_x4(ah[mi], saddr(&As[0][r][kc]));
                ldsm_x4(al[mi], saddr(&As[1][r][kc]));
            }
            // B fragments (k-major via ldmatrix.x4.trans; 2 n8-tiles per instr)
#pragma unroll
            for (int g = 0; g < 2; g++) {
                const int kr = ks + (lane & 7) + (((lane >> 3) & 1) << 3);
                const int nn = wn * 32 + g * 16 + (((lane >> 4) & 1) << 3);
                uint32_t tmp[4];
                ldsm_x4t(tmp, saddr(&Bs[0][kr][nn]));
                bh[g * 2 + 0][0] = tmp[0]; bh[g * 2 + 0][1] = tmp[1];
                bh[g * 2 + 1][0] = tmp[2]; bh[g * 2 + 1][1] = tmp[3];
                ldsm_x4t(tmp, saddr(&Bs[1][kr][nn]));
                bl[g * 2 + 0][0] = tmp[0]; bl[g * 2 + 0][1] = tmp[1];
                bl[g * 2 + 1][0] = tmp[2]; bl[g * 2 + 1][1] = tmp[3];
            }
            // 3-pass split-precision accumulate
#pragma unroll
            for (int mi = 0; mi < 4; mi++)
#pragma unroll
                for (int ni = 0; ni < 4; ni++) {
                    mma_bf16(acc[mi][ni], ah[mi], bh[ni]);
                    mma_bf16(acc[mi][ni], ah[mi], bl[ni]);
                    mma_bf16(acc[mi][ni], al[mi], bh[ni]);
                }
        }
        __syncthreads();
    }

    // ---- epilogue ----
#pragma unroll
    for (int mi = 0; mi < 4; mi++) {
        const int r0 = brow + wm * 64 + mi * 16 + (lane >> 2);
#pragma unroll
        for (int ni = 0; ni < 4; ni++) {
            const int c0 = bcol + wn * 32 + ni * 8 + (lane & 3) * 2;
            if (c0 < N) {
                const float b0 = bias ? bias[c0] : 0.f;
                const float b1 = bias ? bias[c0 + 1] : 0.f;
                const float* a = acc[mi][ni];
                const float v00 = a[0] + b0, v01 = a[1] + b1;
                const float v10 = a[2] + b0, v11 = a[3] + b1;
                C[(size_t)r0 * ldc + c0]           = v00;
                C[(size_t)r0 * ldc + c0 + 1]       = v01;
                C[(size_t)(r0 + 8) * ldc + c0]     = v10;
                C[(size_t)(r0 + 8) * ldc + c0 + 1] = v11;
                if (VSQ) {
                    const int h = ldc >> 1;
                    C[(size_t)r0 * ldc + h + c0]           = v00 * v00;
                    C[(size_t)r0 * ldc + h + c0 + 1]       = v01 * v01;
                    C[(size_t)(r0 + 8) * ldc + h + c0]     = v10 * v10;
                    C[(size_t)(r0 + 8) * ldc + h + c0 + 1] = v11 * v11;
                }
            }
        }
    }
}

// ---------------- row softmax (4096-wide rows, one block/row) ----------------
__global__ __launch_bounds__(256)
void softmax_kernel(float* __restrict__ A) {
    float* p = A + (size_t)blockIdx.x * NPIX;
    const int t = threadIdx.x;
    float v[16];
    float mx = -3.0e38f;
#pragma unroll
    for (int i = 0; i < 16; i++) {
        v[i] = p[t + 256 * i];
        mx = fmaxf(mx, v[i]);
    }
    __shared__ float red[8];
#pragma unroll
    for (int o = 16; o > 0; o >>= 1) mx = fmaxf(mx, __shfl_xor_sync(0xffffffffu, mx, o));
    if ((t & 31) == 0) red[t >> 5] = mx;
    __syncthreads();
    mx = red[0];
#pragma unroll
    for (int w = 1; w < 8; w++) mx = fmaxf(mx, red[w]);

    float s = 0.f;
#pragma unroll
    for (int i = 0; i < 16; i++) {
        v[i] = __expf(v[i] - mx);
        s += v[i];
    }
#pragma unroll
    for (int o = 16; o > 0; o >>= 1) s += __shfl_xor_sync(0xffffffffu, s, o);
    __syncthreads();
    if ((t & 31) == 0) red[t >> 5] = s;
    __syncthreads();
    s = red[0];
#pragma unroll
    for (int w = 1; w < 8; w++) s += red[w];
    const float inv = 1.f / s;
#pragma unroll
    for (int i = 0; i < 16; i++) p[t + 256 * i] = v[i] * inv;
}

// ---------------- epilogue: out = sqrt(max(E2 - M^2, 1e-9)) * inorm(content) + M ----------------
__global__ __launch_bounds__(256)
void epilogue_kernel(const float* __restrict__ content, float* __restrict__ out) {
    size_t i4 = ((size_t)blockIdx.x * 256 + threadIdx.x) * 4;
    const size_t total = (size_t)BB * NPIX * C0;
    if (i4 >= total) return;
    int c = (int)(i4 % C0);
    size_t bn = i4 / C0;
    int b = (int)(bn >> 12);
    float4 m4 = *reinterpret_cast<const float4*>(g_MV + bn * NVV + c);
    float4 e4 = *reinterpret_cast<const float4*>(g_MV + bn * NVV + C0 + c);
    float4 x4 = *reinterpret_cast<const float4*>(content + i4);
    const float* meanp = g_norms + b * C0 + c;
    const float* rstdp = g_norms + BB * C0 + b * C0 + c;
    float4 o;
    o.x = sqrtf(fmaxf(e4.x - m4.x * m4.x, 1e-9f)) * ((x4.x - meanp[0]) * rstdp[0]) + m4.x;
    o.y = sqrtf(fmaxf(e4.y - m4.y * m4.y, 1e-9f)) * ((x4.y - meanp[1]) * rstdp[1]) + m4.y;
    o.z = sqrtf(fmaxf(e4.z - m4.z * m4.z, 1e-9f)) * ((x4.z - meanp[2]) * rstdp[2]) + m4.z;
    o.w = sqrtf(fmaxf(e4.w - m4.w * m4.w, 1e-9f)) * ((x4.w - meanp[3]) * rstdp[3]) + m4.w;
    *reinterpret_cast<float4*>(out + i4) = o;
}

// ---------------- launch ----------------
extern "C" void kernel_launch(void* const* d_in, const int* in_sizes, int n_in,
                              void* d_out, int out_size) {
    (void)in_sizes; (void)n_in; (void)out_size;
    const float* content   = (const float*)d_in[0];
    const float* style     = (const float*)d_in[1];
    const float* comb_cont = (const float*)d_in[2];
    const float* comb_sty  = (const float*)d_in[3];
    const float* Wq = (const float*)d_in[4];
    const float* bq = (const float*)d_in[5];
    const float* Wk = (const float*)d_in[6];
    const float* bk = (const float*)d_in[7];
    const float* Wv = (const float*)d_in[8];
    const float* bv = (const float*)d_in[9];
    float* out = (float*)d_out;

    float *Xqn, *Xkn, *Qp, *Kp, *VVp, *Ap, *MVp, *sums, *norms;
    cudaGetSymbolAddress((void**)&Xqn,   g_Xqn);
    cudaGetSymbolAddress((void**)&Xkn,   g_Xkn);
    cudaGetSymbolAddress((void**)&Qp,    g_Q);
    cudaGetSymbolAddress((void**)&Kp,    g_Kk);
    cudaGetSymbolAddress((void**)&VVp,   g_VV);
    cudaGetSymbolAddress((void**)&Ap,    g_A);
    cudaGetSymbolAddress((void**)&MVp,   g_MV);
    cudaGetSymbolAddress((void**)&sums,  g_sums);
    cudaGetSymbolAddress((void**)&norms, g_norms);

    // 1) instance-norm statistics for content / comb_cont / comb_sty
    zero_kernel<<<(NSTAT + 255) / 256, 256>>>(sums, NSTAT);
    stats_partial<<<dim3(4, 32, BB), 128>>>(content,   sums,                             sums + BB * C0,                   C0);
    stats_partial<<<dim3(8, 32, BB), 128>>>(comb_cont, sums + 2 * BB * C0,               sums + 2 * BB * C0 + BB * C1,     C1);
    stats_partial<<<dim3(8, 32, BB), 128>>>(comb_sty,  sums + 2 * BB * C0 + 2 * BB * C1, sums + 2 * BB * C0 + 3 * BB * C1, C1);
    stats_finalize_kernel<<<(BB * C0 + 2 * BB * C1 + 255) / 256, 256>>>();

    // 2) normalize the comb tensors
    const int nrm_blocks = (int)(((size_t)BB * NPIX * C1 / 4 + 255) / 256);
    normalize_kernel<<<nrm_blocks, 256>>>(comb_cont, Xqn, norms + 2 * BB * C0,               norms + 2 * BB * C0 + BB * C1);
    normalize_kernel<<<nrm_blocks, 256>>>(comb_sty,  Xkn, norms + 2 * BB * C0 + 2 * BB * C1, norms + 2 * BB * C0 + 3 * BB * C1);

    // 3) projections (tensor-core bf16x3): Q, K (4096x960x960), V+V^2 (4096x512x512)
    mma_gemm<false><<<dim3(8, 32, BB), 256>>>(Xqn,  Wq, bq, Qp,  NPIX, C1, C1,
                                              (size_t)NPIX * C1, 0, (size_t)NPIX * C1, C1);
    mma_gemm<false><<<dim3(8, 32, BB), 256>>>(Xkn,  Wk, bk, Kp,  NPIX, C1, C1,
                                              (size_t)NPIX * C1, 0, (size_t)NPIX * C1, C1);
    mma_gemm<true ><<<dim3(4, 32, BB), 256>>>(style, Wv, bv, VVp, NPIX, C0, C0,
                                              (size_t)NPIX * C0, 0, (size_t)NPIX * NVV, NVV);

    // 3b) K -> K^T  (so logits GEMM is NN); Xkn buffer is free now, reuse as Kt
    transpose_kernel<<<dim3(C1 / 32, NPIX / 32, BB), dim3(32, 8)>>>(Kp, Xkn);

    // 4) logits = Q @ K^T  (4096x4096x960), then row softmax
    mma_gemm<false><<<dim3(32, 32, BB), 256>>>(Qp, Xkn, nullptr, Ap, NPIX, NPIX, C1,
                                               (size_t)NPIX * C1, (size_t)NPIX * C1,
                                               (size_t)NPIX * NPIX, NPIX);
    softmax_kernel<<<BB * NPIX, 256>>>(Ap);

    // 5) [M | E2] = A @ [V | V^2]   (4096x1024x4096, single pass over A)
    mma_gemm<false><<<dim3(8, 32, BB), 256>>>(Ap, VVp, nullptr, MVp, NPIX, NVV, NPIX,
                                              (size_t)NPIX * NPIX, (size_t)NPIX * NVV,
                                              (size_t)NPIX * NVV, NVV);

    // 6) out = S * inorm(content) + M
    epilogue_kernel<<<(int)(((size_t)BB * NPIX * C0 / 4 + 255) / 256), 256>>>(content, out);
}